// round 8
// baseline (speedup 1.0000x reference)
#include <cuda_runtime.h>

// CollaborativeRNN (GRU-like): B=32, T=256, H=1024, V=10001
// out = [h_final (B*H) | logits (B*T*V)]  (float32)

#define BB 32
#define TT 256
#define HH 1024
#define H2 2048
#define VV 10001
#define NB 128    // persistent grid size (<=148 SMs, 1 block/SM by smem)

typedef unsigned long long u64;

// Scratch (device globals; no allocations allowed)
__device__ float g_h[HH * BB];            // h transposed: g_h[k*BB + b]
__device__ float g_rh[HH * BB];           // (r * h) transposed
__device__ float g_u[HH * BB];            // u gate transposed
__device__ float g_states[BB * TT * HH];  // states row-major [B*T, H]
__device__ int   g_items[BB * TT];        // canonicalized int32 item ids
__device__ int   g_nzodd;                 // dtype-detect flag
__device__ int   g_root;                  // barrier root counter
__device__ int   g_gcnt[8 * 32];          // 8 group counters, 128B padded
__device__ volatile int g_gen;            // barrier generation

__device__ __forceinline__ u64 fma2(u64 a, u64 b, u64 c) {
    u64 d;
    asm("fma.rn.f32x2 %0, %1, %2, %3;" : "=l"(d) : "l"(a), "l"(b), "l"(c));
    return d;
}
__device__ __forceinline__ u64 add2(u64 a, u64 b) {
    u64 d;
    asm("add.rn.f32x2 %0, %1, %2;" : "=l"(d) : "l"(a), "l"(b));
    return d;
}
__device__ __forceinline__ u64 pack2(float x, float y) {
    u64 d;
    asm("mov.b64 %0, {%1, %2};" : "=l"(d) : "f"(x), "f"(y));
    return d;
}
__device__ __forceinline__ void unpack2(u64 v, float &x, float &y) {
    asm("mov.b64 {%0, %1}, %2;" : "=f"(x), "=f"(y) : "l"(v));
}

// ---------------------------------------------------------------------------
__global__ void k_init(const float* __restrict__ h0) {
    int i = blockIdx.x * blockDim.x + threadIdx.x;
    if (i == 0) { g_nzodd = 0; g_root = 0; g_gen = 0; }
    if (i < 8) g_gcnt[i * 32] = 0;
    if (i < BB * HH) {
        int b = i / HH, k = i % HH;
        g_h[k * BB + b] = h0[i];
    }
}

__global__ void k_detect(const int* __restrict__ w) {
    int i = blockIdx.x * blockDim.x + threadIdx.x;
    if (i < (BB * TT) / 2) {
        if (w[2 * i + 1] != 0) atomicOr(&g_nzodd, 1);
    }
}
__global__ void k_convert(const int* __restrict__ w) {
    int i = blockIdx.x * blockDim.x + threadIdx.x;
    if (i < BB * TT) g_items[i] = g_nzodd ? w[i] : w[2 * i];
}

// ---------------------------------------------------------------------------
// Two-level grid barrier: 8 padded group counters (16 blocks each) + root.
__device__ __forceinline__ void gridbar(int blk) {
    __syncthreads();
    if (threadIdx.x == 0) {
        __threadfence();
        int gen = g_gen;
        bool released = false;
        int grp = blk >> 4;                       // 0..7
        if (atomicAdd(&g_gcnt[grp * 32], 1) == 15) {
            atomicExch(&g_gcnt[grp * 32], 0);
            if (atomicAdd(&g_root, 1) == 7) {
                atomicExch(&g_root, 0);
                __threadfence();
                g_gen = gen + 1;
                released = true;
            }
        }
        if (!released) {
            while (g_gen == gen) { __nanosleep(32); }
        }
        __threadfence();
    }
    __syncthreads();
}

// ---------------------------------------------------------------------------
// Persistent recurrence kernel. 128 blocks x 512 threads.
// Block owns: 8 col-pairs of W_ru (cols blk*16..+15) and 4 col-pairs of W_c
// (cols blk*8..+7), resident in smem for all 256 steps.
// Staging is double-buffered: 4 chunks of 256k x 32b (32 KB) per phase,
// next chunk prefetched to registers while computing the current one.
// Dynamic smem:
//   Wa : 8192 u64  (64 KB)
//   Wb : 4096 u64  (32 KB)
//   hs : 2 x 8192 f32 (64 KB)  double-buffered stage
//   red: 2048 u64  (16 KB)
__global__ __launch_bounds__(512) void k_rnn(
    const float* __restrict__ Eru, const float* __restrict__ bru,
    const float* __restrict__ Ec,  const float* __restrict__ bc,
    const float* __restrict__ Wru, const float* __restrict__ Wc)
{
    extern __shared__ char smem[];
    u64*   Wa  = (u64*)smem;                     // 65536 B
    u64*   Wb  = (u64*)(smem + 65536);           // 32768 B
    float* hs0 = (float*)(smem + 98304);         // 32768 B
    float* hs1 = (float*)(smem + 131072);        // 32768 B
    u64*   red = (u64*)(smem + 163840);          // 16384 B

    const int tid  = threadIdx.x;
    const int lane = tid & 31;
    const int wid  = tid >> 5;                   // 0..15
    const int blk  = blockIdx.x;

    // One-time weight load into smem (packed col-pairs)
    for (int i = tid; i < 8192; i += 512) {
        int k = i >> 3, cpl = i & 7;
        float2 w = *reinterpret_cast<const float2*>(&Wru[k * H2 + blk * 16 + 2 * cpl]);
        Wa[k * 8 + cpl] = pack2(w.x, w.y);
    }
    for (int i = tid; i < 4096; i += 512) {
        int k = i >> 2, cpl = i & 3;
        float2 w = *reinterpret_cast<const float2*>(&Wc[k * HH + blk * 8 + 2 * cpl]);
        Wb[k * 4 + cpl] = pack2(w.x, w.y);
    }

    // Output roles (guarded: only low threads own output columns)
    const int cpO   = tid >> 5;
    const int col0A = blk * 16 + 2 * cpO;         // valid tid<256
    const int col0B = blk * 8 + 2 * cpO;          // valid tid<128
    float2 bA = make_float2(0.f, 0.f), bB = make_float2(0.f, 0.f);
    if (tid < 256) bA = *reinterpret_cast<const float2*>(&bru[col0A]);
    if (tid < 128) bB = *reinterpret_cast<const float2*>(&bc[col0B]);

    // Compute-split roles
    const int teamA = wid >> 3;                   // 0..1 -> cp half
    const int wkA   = wid & 7;                    // k-range within chunk (A)

    __syncthreads();

    for (int t = 0; t < TT; t++) {
        // ================= Phase A: ru gates =================
        float2 eA = make_float2(0.f, 0.f);
        if (tid < 256) {
            int itA = g_items[lane * TT + t];
            eA = *reinterpret_cast<const float2*>(&Eru[itA * H2 + col0A]);
        }

        u64 a0 = 0ull, a1 = 0ull, a2 = 0ull, a3 = 0ull;
        {
            // Pipelined staging: chunk = 256k x 32b = 2048 float4; 4/thread.
            float4 pf0, pf1, pf2, pf3;
            const float4* gsrc = (const float4*)g_h;
            pf0 = __ldcg(&gsrc[tid]);
            pf1 = __ldcg(&gsrc[tid + 512]);
            pf2 = __ldcg(&gsrc[tid + 1024]);
            pf3 = __ldcg(&gsrc[tid + 1536]);
            float* buf = hs0;
            ((float4*)buf)[tid]        = pf0;
            ((float4*)buf)[tid + 512]  = pf1;
            ((float4*)buf)[tid + 1024] = pf2;
            ((float4*)buf)[tid + 1536] = pf3;
            __syncthreads();
#pragma unroll
            for (int c = 0; c < 4; c++) {
                if (c < 3) {
                    const float4* nsrc = (const float4*)(g_h + (c + 1) * 256 * BB);
                    pf0 = __ldcg(&nsrc[tid]);
                    pf1 = __ldcg(&nsrc[tid + 512]);
                    pf2 = __ldcg(&nsrc[tid + 1024]);
                    pf3 = __ldcg(&nsrc[tid + 1536]);
                }
                float* cur = (c & 1) ? hs1 : hs0;
                const int kbase = wkA * 32;
#pragma unroll 4
                for (int kl = kbase; kl < kbase + 32; kl++) {
                    float hv = cur[kl * 32 + lane];
                    u64 hd = pack2(hv, hv);
                    ulonglong2 w01 = *reinterpret_cast<const ulonglong2*>(
                        &Wa[(c * 256 + kl) * 8 + teamA * 4]);
                    ulonglong2 w23 = *reinterpret_cast<const ulonglong2*>(
                        &Wa[(c * 256 + kl) * 8 + teamA * 4 + 2]);
                    a0 = fma2(hd, w01.x, a0);
                    a1 = fma2(hd, w01.y, a1);
                    a2 = fma2(hd, w23.x, a2);
                    a3 = fma2(hd, w23.y, a3);
                }
                if (c < 3) {
                    float* nxt = (c & 1) ? hs0 : hs1;
                    ((float4*)nxt)[tid]        = pf0;
                    ((float4*)nxt)[tid + 512]  = pf1;
                    ((float4*)nxt)[tid + 1024] = pf2;
                    ((float4*)nxt)[tid + 1536] = pf3;
                    __syncthreads();
                }
            }
        }
        // partials: red[wkA][cp = teamA*4+q][lane]
        red[(wkA * 8 + teamA * 4 + 0) * 32 + lane] = a0;
        red[(wkA * 8 + teamA * 4 + 1) * 32 + lane] = a1;
        red[(wkA * 8 + teamA * 4 + 2) * 32 + lane] = a2;
        red[(wkA * 8 + teamA * 4 + 3) * 32 + lane] = a3;
        __syncthreads();
        if (tid < 256) {
            int cp = cpO;                          // 0..7
            u64 s = red[cp * 32 + lane];
#pragma unroll
            for (int w = 1; w < 8; w++)
                s = add2(s, red[(w * 8 + cp) * 32 + lane]);
            float p0, p1;
            unpack2(s, p0, p1);
            p0 += eA.x + bA.x;
            p1 += eA.y + bA.y;
            p0 = 1.0f / (1.0f + __expf(-p0));
            p1 = 1.0f / (1.0f + __expf(-p1));
            if (blk * 8 + cp < 512) {  // r gates -> r*h
                float h0 = __ldcg(&g_h[col0A * 32 + lane]);
                float h1 = __ldcg(&g_h[(col0A + 1) * 32 + lane]);
                __stcg(&g_rh[col0A * 32 + lane], p0 * h0);
                __stcg(&g_rh[(col0A + 1) * 32 + lane], p1 * h1);
            } else {                   // u gates
                __stcg(&g_u[(col0A - HH) * 32 + lane], p0);
                __stcg(&g_u[(col0A - HH + 1) * 32 + lane], p1);
            }
        }
        // Prefetch phase-B embedding gather before the barrier (independent).
        float2 eB = make_float2(0.f, 0.f);
        if (tid < 128) {
            int itB = g_items[lane * TT + t];
            eB = *reinterpret_cast<const float2*>(&Ec[itB * HH + col0B]);
        }
        gridbar(blk);

        // ================= Phase B: candidate + h update =================
        u64 b0 = 0ull, b1 = 0ull, b2 = 0ull, b3 = 0ull;
        {
            float4 pf0, pf1, pf2, pf3;
            const float4* gsrc = (const float4*)g_rh;
            pf0 = __ldcg(&gsrc[tid]);
            pf1 = __ldcg(&gsrc[tid + 512]);
            pf2 = __ldcg(&gsrc[tid + 1024]);
            pf3 = __ldcg(&gsrc[tid + 1536]);
            ((float4*)hs0)[tid]        = pf0;
            ((float4*)hs0)[tid + 512]  = pf1;
            ((float4*)hs0)[tid + 1024] = pf2;
            ((float4*)hs0)[tid + 1536] = pf3;
            __syncthreads();
#pragma unroll
            for (int c = 0; c < 4; c++) {
                if (c < 3) {
                    const float4* nsrc = (const float4*)(g_rh + (c + 1) * 256 * BB);
                    pf0 = __ldcg(&nsrc[tid]);
                    pf1 = __ldcg(&nsrc[tid + 512]);
                    pf2 = __ldcg(&nsrc[tid + 1024]);
                    pf3 = __ldcg(&nsrc[tid + 1536]);
                }
                float* cur = (c & 1) ? hs1 : hs0;
                const int kbase = wid * 16;
#pragma unroll 4
                for (int kl = kbase; kl < kbase + 16; kl++) {
                    float rv = cur[kl * 32 + lane];
                    u64 rd = pack2(rv, rv);
                    ulonglong2 w01 = *reinterpret_cast<const ulonglong2*>(
                        &Wb[(c * 256 + kl) * 4]);
                    ulonglong2 w23 = *reinterpret_cast<const ulonglong2*>(
                        &Wb[(c * 256 + kl) * 4 + 2]);
                    b0 = fma2(rd, w01.x, b0);
                    b1 = fma2(rd, w01.y, b1);
                    b2 = fma2(rd, w23.x, b2);
                    b3 = fma2(rd, w23.y, b3);
                }
                if (c < 3) {
                    float* nxt = (c & 1) ? hs0 : hs1;
                    ((float4*)nxt)[tid]        = pf0;
                    ((float4*)nxt)[tid + 512]  = pf1;
                    ((float4*)nxt)[tid + 1024] = pf2;
                    ((float4*)nxt)[tid + 1536] = pf3;
                    __syncthreads();
                }
            }
        }
        // partials: red[wid][cp 0..3][lane]
        red[(wid * 4 + 0) * 32 + lane] = b0;
        red[(wid * 4 + 1) * 32 + lane] = b1;
        red[(wid * 4 + 2) * 32 + lane] = b2;
        red[(wid * 4 + 3) * 32 + lane] = b3;
        __syncthreads();
        if (tid < 128) {
            int cp = cpO;                          // 0..3
            u64 s = red[cp * 32 + lane];
#pragma unroll
            for (int w = 1; w < 16; w++)
                s = add2(s, red[(w * 4 + cp) * 32 + lane]);
            float c0, c1;
            unpack2(s, c0, c1);
            c0 = tanhf(c0 + eB.x + bB.x);
            c1 = tanhf(c1 + eB.y + bB.y);
            float u0 = __ldcg(&g_u[col0B * 32 + lane]);
            float u1 = __ldcg(&g_u[(col0B + 1) * 32 + lane]);
            float h0 = __ldcg(&g_h[col0B * 32 + lane]);
            float h1 = __ldcg(&g_h[(col0B + 1) * 32 + lane]);
            float hn0 = u0 * h0 + (1.0f - u0) * c0;
            float hn1 = u1 * h1 + (1.0f - u1) * c1;
            __stcg(&g_h[col0B * 32 + lane], hn0);
            __stcg(&g_h[(col0B + 1) * 32 + lane], hn1);
            __stcg(reinterpret_cast<float2*>(
                       &g_states[(lane * TT + t) * HH + col0B]),
                   make_float2(hn0, hn1));
        }
        gridbar(blk);
    }
}

// ---------------------------------------------------------------------------
// Output GEMM: C[8192, V] = states[8192, H] @ W_out[H, V]
// 128m x 128n tile, 256 threads, micro 8m x 8n. A staged duplicated (a,a).
__global__ __launch_bounds__(256) void k_gemm(
    const float* __restrict__ Wo, float* __restrict__ C)
{
    const int tx = threadIdx.x & 15;   // n group: n0 = tx*8
    const int ty = threadIdx.x >> 4;   // m group: m0 = ty*8
    const int mt = blockIdx.x * 128;
    const int nt = blockIdx.y * 128;

    __shared__ u64   Asd[16][128];     // 16 KB, (a,a) dup [k][m]
    __shared__ float Bs[16][128];      //  8 KB

    u64 acc[8][4];
#pragma unroll
    for (int i = 0; i < 8; i++)
#pragma unroll
        for (int j = 0; j < 4; j++) acc[i][j] = 0ull;

    const int am  = threadIdx.x >> 1;        // 0..127
    const int ak4 = (threadIdx.x & 1) * 8;   // 0 or 8

    for (int k0 = 0; k0 < HH; k0 += 16) {
        float4 av0 = *reinterpret_cast<const float4*>(
            &g_states[(mt + am) * HH + k0 + ak4]);
        float4 av1 = *reinterpret_cast<const float4*>(
            &g_states[(mt + am) * HH + k0 + ak4 + 4]);
        float bv[8];
#pragma unroll
        for (int j = 0; j < 8; j++) {
            int idx = threadIdx.x + j * 256;      // 0..2047
            int bk = idx >> 7, bn = idx & 127;
            int ncol = nt + bn;
            bv[j] = (ncol < VV) ? Wo[(k0 + bk) * VV + ncol] : 0.0f;
        }
        __syncthreads();
        Asd[ak4 + 0][am] = pack2(av0.x, av0.x);
        Asd[ak4 + 1][am] = pack2(av0.y, av0.y);
        Asd[ak4 + 2][am] = pack2(av0.z, av0.z);
        Asd[ak4 + 3][am] = pack2(av0.w, av0.w);
        Asd[ak4 + 4][am] = pack2(av1.x, av1.x);
        Asd[ak4 + 5][am] = pack2(av1.y, av1.y);
        Asd[ak4 + 6][am] = pack2(av1.z, av1.z);
        Asd[ak4 + 7][am] = pack2(av1.w, av1.w);
#pragma unroll
        for (int j = 0; j < 8; j++) {
            int idx = threadIdx.x + j * 256;
            Bs[idx >> 7][idx & 127] = bv[j];
        }
        __syncthreads();
#pragma unroll
        for (int k = 0; k < 16; k++) {
            ulonglong2 a01 = *reinterpret_cast<const ulonglong2*>(&Asd[k][ty * 8]);
            ulonglong2 a23 = *reinterpret_cast<const ulonglong2*>(&Asd[k][ty * 8 + 2]);
            ulonglong2 a45 = *reinterpret_cast<const ulonglong2*>(&Asd[k][ty * 8 + 4]);
            ulonglong2 a67 = *reinterpret_cast<const ulonglong2*>(&Asd[k][ty * 8 + 6]);
            ulonglong2 bl = *reinterpret_cast<const ulonglong2*>(&Bs[k][tx * 8]);
            ulonglong2 bh = *reinterpret_cast<const ulonglong2*>(&Bs[k][tx * 8 + 4]);
            u64 a[8] = {a01.x, a01.y, a23.x, a23.y, a45.x, a45.y, a67.x, a67.y};
#pragma unroll
            for (int i = 0; i < 8; i++) {
                acc[i][0] = fma2(a[i], bl.x, acc[i][0]);
                acc[i][1] = fma2(a[i], bl.y, acc[i][1]);
                acc[i][2] = fma2(a[i], bh.x, acc[i][2]);
                acc[i][3] = fma2(a[i], bh.y, acc[i][3]);
            }
        }
    }

    // Epilogue (scalar stores; V=10001 rows are 16B-misaligned)
#pragma unroll
    for (int i = 0; i < 8; i++) {
        int m = mt + ty * 8 + i;
        float* row = &C[m * VV];
#pragma unroll
        for (int j = 0; j < 4; j++) {
            float c0, c1;
            unpack2(acc[i][j], c0, c1);
            int n = nt + tx * 8 + j * 2;
            if (n < VV)     row[n]     = c0;
            if (n + 1 < VV) row[n + 1] = c1;
        }
    }
}

// ---------------------------------------------------------------------------
// h_final: g_h [H,B] -> out [B,H]
__global__ void k_hfinal(float* __restrict__ out) {
    int i = blockIdx.x * blockDim.x + threadIdx.x;
    if (i < BB * HH) {
        int b = i / HH, k = i % HH;
        out[i] = g_h[k * BB + b];
    }
}

// ---------------------------------------------------------------------------
extern "C" void kernel_launch(void* const* d_in, const int* in_sizes, int n_in,
                              void* d_out, int out_size)
{
    const int*   items_raw = (const int*)d_in[0];
    const float* h0   = (const float*)d_in[1];
    const float* E_ru = (const float*)d_in[2];
    const float* W_ru = (const float*)d_in[3];
    const float* b_ru = (const float*)d_in[4];
    const float* E_c  = (const float*)d_in[5];
    const float* W_c  = (const float*)d_in[6];
    const float* b_c  = (const float*)d_in[7];
    const float* W_out = (const float*)d_in[8];

    float* out = (float*)d_out;
    float* logits = out + BB * HH;

    cudaFuncSetAttribute(k_rnn, cudaFuncAttributeMaxDynamicSharedMemorySize,
                         180224);

    k_init<<<(BB * HH + 255) / 256, 256>>>(h0);
    k_detect<<<(BB * TT / 2 + 255) / 256, 256>>>(items_raw);
    k_convert<<<(BB * TT + 255) / 256, 256>>>(items_raw);

    k_rnn<<<NB, 512, 180224>>>(E_ru, b_ru, E_c, b_c, W_ru, W_c);

    dim3 ggrid((BB * TT) / 128, (VV + 127) / 128);
    k_gemm<<<ggrid, 256>>>(W_out, logits);

    k_hfinal<<<(BB * HH + 255) / 256, 256>>>(out);
}

// round 11
// speedup vs baseline: 1.0290x; 1.0290x over previous
#include <cuda_runtime.h>
#include <cuda_bf16.h>
#include <cstdint>

// CollaborativeRNN (GRU-like): B=32, T=256, H=1024, V=10001
// out = [h_final (B*H) | logits (B*T*V)]  (float32)

#define BB 32
#define TT 256
#define HH 1024
#define H2 2048
#define VV 10001
#define NB 128
#define NPAD 10112  // 79 * 128

typedef unsigned long long u64;

__device__ float g_h[HH * BB];
__device__ float g_rh[HH * BB];
__device__ float g_u[HH * BB];
__device__ float g_states[BB * TT * HH];
__device__ int   g_items[BB * TT];
__device__ int   g_nzodd;
__device__ int   g_count;
__device__ volatile int g_gen;
__device__ __nv_bfloat16 g_Shi[BB * TT * HH];
__device__ __nv_bfloat16 g_Slo[BB * TT * HH];
__device__ __nv_bfloat16 g_WThi[NPAD * HH];   // transposed W_out [n][k]
__device__ __nv_bfloat16 g_WTlo[NPAD * HH];

__device__ __forceinline__ u64 fma2(u64 a, u64 b, u64 c) {
    u64 d;
    asm("fma.rn.f32x2 %0, %1, %2, %3;" : "=l"(d) : "l"(a), "l"(b), "l"(c));
    return d;
}
__device__ __forceinline__ u64 add2(u64 a, u64 b) {
    u64 d;
    asm("add.rn.f32x2 %0, %1, %2;" : "=l"(d) : "l"(a), "l"(b));
    return d;
}
__device__ __forceinline__ u64 pack2(float x, float y) {
    u64 d;
    asm("mov.b64 %0, {%1, %2};" : "=l"(d) : "f"(x), "f"(y));
    return d;
}
__device__ __forceinline__ void unpack2(u64 v, float &x, float &y) {
    asm("mov.b64 {%0, %1}, %2;" : "=f"(x), "=f"(y) : "l"(v));
}
__device__ __forceinline__ uint32_t smem_u32(const void* p) {
    uint32_t a;
    asm("{ .reg .u64 t; cvta.to.shared.u64 t, %1; cvt.u32.u64 %0, t; }"
        : "=r"(a) : "l"(p));
    return a;
}
__device__ __forceinline__ void ldsm_x4(uint32_t* r, uint32_t addr) {
    asm volatile("ldmatrix.sync.aligned.m8n8.x4.shared.b16 {%0,%1,%2,%3}, [%4];"
                 : "=r"(r[0]), "=r"(r[1]), "=r"(r[2]), "=r"(r[3]) : "r"(addr));
}
__device__ __forceinline__ void mma16816(float* c, const uint32_t* a,
                                         const uint32_t* b) {
    asm volatile(
        "mma.sync.aligned.m16n8k16.row.col.f32.bf16.bf16.f32 "
        "{%0,%1,%2,%3}, {%4,%5,%6,%7}, {%8,%9}, {%0,%1,%2,%3};"
        : "+f"(c[0]), "+f"(c[1]), "+f"(c[2]), "+f"(c[3])
        : "r"(a[0]), "r"(a[1]), "r"(a[2]), "r"(a[3]), "r"(b[0]), "r"(b[1]));
}

// ---------------------------------------------------------------------------
__global__ void k_init(const float* __restrict__ h0) {
    int i = blockIdx.x * blockDim.x + threadIdx.x;
    if (i == 0) { g_nzodd = 0; g_count = 0; g_gen = 0; }
    if (i < BB * HH) {
        int b = i / HH, k = i % HH;
        g_h[k * BB + b] = h0[i];
    }
}
__global__ void k_detect(const int* __restrict__ w) {
    int i = blockIdx.x * blockDim.x + threadIdx.x;
    if (i < (BB * TT) / 2) {
        if (w[2 * i + 1] != 0) atomicOr(&g_nzodd, 1);
    }
}
__global__ void k_convert(const int* __restrict__ w) {
    int i = blockIdx.x * blockDim.x + threadIdx.x;
    if (i < BB * TT) g_items[i] = g_nzodd ? w[i] : w[2 * i];
}

// ---------------------------------------------------------------------------
__device__ __forceinline__ void gridbar() {
    __syncthreads();
    if (threadIdx.x == 0) {
        __threadfence();
        int gen = g_gen;
        if (atomicAdd(&g_count, 1) == NB - 1) {
            atomicExch(&g_count, 0);
            __threadfence();
            g_gen = gen + 1;
        } else {
            while (g_gen == gen) { __nanosleep(64); }
            __threadfence();
        }
    }
    __syncthreads();
}

// ---------------------------------------------------------------------------
// Persistent recurrence kernel (R7 variant: best measured). 128 x 512.
__global__ __launch_bounds__(512) void k_rnn(
    const float* __restrict__ Eru, const float* __restrict__ bru,
    const float* __restrict__ Ec,  const float* __restrict__ bc,
    const float* __restrict__ Wru, const float* __restrict__ Wc)
{
    extern __shared__ char smem[];
    u64*   Wa  = (u64*)smem;
    u64*   Wb  = (u64*)(smem + 65536);
    float* hs  = (float*)(smem + 98304);
    u64*   red = (u64*)(smem + 163840);

    const int tid  = threadIdx.x;
    const int lane = tid & 31;
    const int wid  = tid >> 5;
    const int blk  = blockIdx.x;

    for (int i = tid; i < 8192; i += 512) {
        int k = i >> 3, cpl = i & 7;
        float2 w = *reinterpret_cast<const float2*>(&Wru[k * H2 + blk * 16 + 2 * cpl]);
        Wa[k * 8 + cpl] = pack2(w.x, w.y);
    }
    for (int i = tid; i < 4096; i += 512) {
        int k = i >> 2, cpl = i & 3;
        float2 w = *reinterpret_cast<const float2*>(&Wc[k * HH + blk * 8 + 2 * cpl]);
        Wb[k * 4 + cpl] = pack2(w.x, w.y);
    }

    const int cpO   = tid >> 5;
    const int col0A = blk * 16 + 2 * cpO;
    const int col0B = blk * 8 + 2 * cpO;
    float2 bA = make_float2(0.f, 0.f), bB = make_float2(0.f, 0.f);
    if (tid < 256) bA = *reinterpret_cast<const float2*>(&bru[col0A]);
    if (tid < 128) bB = *reinterpret_cast<const float2*>(&bc[col0B]);

    const int teamA = wid >> 3;
    const int wkA   = wid & 7;

    __syncthreads();

    for (int t = 0; t < TT; t++) {
        float2 eA = make_float2(0.f, 0.f);
        if (tid < 256) {
            int itA = g_items[lane * TT + t];
            eA = *reinterpret_cast<const float2*>(&Eru[itA * H2 + col0A]);
        }

        u64 a0 = 0ull, a1 = 0ull, a2 = 0ull, a3 = 0ull;
#pragma unroll
        for (int c = 0; c < 2; c++) {
            __syncthreads();
            const float4* src = (const float4*)(g_h + c * 512 * BB);
#pragma unroll
            for (int j = 0; j < 8; j++)
                ((float4*)hs)[tid + j * 512] = __ldcg(&src[tid + j * 512]);
            __syncthreads();
            const int kbase = wkA * 64;
#pragma unroll 4
            for (int kl = kbase; kl < kbase + 64; kl++) {
                float hv = hs[kl * 32 + lane];
                u64 hd = pack2(hv, hv);
                ulonglong2 w01 = *reinterpret_cast<const ulonglong2*>(
                    &Wa[(c * 512 + kl) * 8 + teamA * 4]);
                ulonglong2 w23 = *reinterpret_cast<const ulonglong2*>(
                    &Wa[(c * 512 + kl) * 8 + teamA * 4 + 2]);
                a0 = fma2(hd, w01.x, a0);
                a1 = fma2(hd, w01.y, a1);
                a2 = fma2(hd, w23.x, a2);
                a3 = fma2(hd, w23.y, a3);
            }
        }
        red[(wkA * 8 + teamA * 4 + 0) * 32 + lane] = a0;
        red[(wkA * 8 + teamA * 4 + 1) * 32 + lane] = a1;
        red[(wkA * 8 + teamA * 4 + 2) * 32 + lane] = a2;
        red[(wkA * 8 + teamA * 4 + 3) * 32 + lane] = a3;
        __syncthreads();
        if (tid < 256) {
            int cp = cpO;
            u64 s = red[cp * 32 + lane];
#pragma unroll
            for (int w = 1; w < 8; w++)
                s = add2(s, red[(w * 8 + cp) * 32 + lane]);
            float p0, p1;
            unpack2(s, p0, p1);
            p0 += eA.x + bA.x;
            p1 += eA.y + bA.y;
            p0 = 1.0f / (1.0f + __expf(-p0));
            p1 = 1.0f / (1.0f + __expf(-p1));
            if (blk * 8 + cp < 512) {
                float h0 = __ldcg(&g_h[col0A * 32 + lane]);
                float h1 = __ldcg(&g_h[(col0A + 1) * 32 + lane]);
                __stcg(&g_rh[col0A * 32 + lane], p0 * h0);
                __stcg(&g_rh[(col0A + 1) * 32 + lane], p1 * h1);
            } else {
                __stcg(&g_u[(col0A - HH) * 32 + lane], p0);
                __stcg(&g_u[(col0A - HH + 1) * 32 + lane], p1);
            }
        }
        float2 eB = make_float2(0.f, 0.f);
        if (tid < 128) {
            int itB = g_items[lane * TT + t];
            eB = *reinterpret_cast<const float2*>(&Ec[itB * HH + col0B]);
        }
        gridbar();

        u64 b0 = 0ull, b1 = 0ull, b2 = 0ull, b3 = 0ull;
#pragma unroll
        for (int c = 0; c < 2; c++) {
            __syncthreads();
            const float4* src = (const float4*)(g_rh + c * 512 * BB);
#pragma unroll
            for (int j = 0; j < 8; j++)
                ((float4*)hs)[tid + j * 512] = __ldcg(&src[tid + j * 512]);
            __syncthreads();
            const int kbase = wid * 32;
#pragma unroll 4
            for (int kl = kbase; kl < kbase + 32; kl++) {
                float rv = hs[kl * 32 + lane];
                u64 rd = pack2(rv, rv);
                ulonglong2 w01 = *reinterpret_cast<const ulonglong2*>(
                    &Wb[(c * 512 + kl) * 4]);
                ulonglong2 w23 = *reinterpret_cast<const ulonglong2*>(
                    &Wb[(c * 512 + kl) * 4 + 2]);
                b0 = fma2(rd, w01.x, b0);
                b1 = fma2(rd, w01.y, b1);
                b2 = fma2(rd, w23.x, b2);
                b3 = fma2(rd, w23.y, b3);
            }
        }
        red[(wid * 4 + 0) * 32 + lane] = b0;
        red[(wid * 4 + 1) * 32 + lane] = b1;
        red[(wid * 4 + 2) * 32 + lane] = b2;
        red[(wid * 4 + 3) * 32 + lane] = b3;
        __syncthreads();
        if (tid < 128) {
            int cp = cpO;
            u64 s = red[cp * 32 + lane];
#pragma unroll
            for (int w = 1; w < 16; w++)
                s = add2(s, red[(w * 4 + cp) * 32 + lane]);
            float c0, c1;
            unpack2(s, c0, c1);
            c0 = tanhf(c0 + eB.x + bB.x);
            c1 = tanhf(c1 + eB.y + bB.y);
            float u0 = __ldcg(&g_u[col0B * 32 + lane]);
            float u1 = __ldcg(&g_u[(col0B + 1) * 32 + lane]);
            float h0 = __ldcg(&g_h[col0B * 32 + lane]);
            float h1 = __ldcg(&g_h[(col0B + 1) * 32 + lane]);
            float hn0 = u0 * h0 + (1.0f - u0) * c0;
            float hn1 = u1 * h1 + (1.0f - u1) * c1;
            __stcg(&g_h[col0B * 32 + lane], hn0);
            __stcg(&g_h[(col0B + 1) * 32 + lane], hn1);
            __stcg(reinterpret_cast<float2*>(
                       &g_states[(lane * TT + t) * HH + col0B]),
                   make_float2(hn0, hn1));
        }
        gridbar();
    }
}

// ---------------------------------------------------------------------------
// bf16 split conversions
__global__ void k_conv_s() {
    int i = blockIdx.x * blockDim.x + threadIdx.x;
    if (i < BB * TT * HH) {
        float x = g_states[i];
        __nv_bfloat16 hi = __float2bfloat16(x);
        g_Shi[i] = hi;
        g_Slo[i] = __float2bfloat16(x - __bfloat162float(hi));
    }
}
__global__ void k_conv_w(const float* __restrict__ Wo) {
    int i = blockIdx.x * blockDim.x + threadIdx.x;
    if (i < NPAD * HH) {
        int n = i >> 10, k = i & 1023;
        float x = (n < VV) ? Wo[k * VV + n] : 0.0f;
        __nv_bfloat16 hi = __float2bfloat16(x);
        g_WThi[n * HH + k] = hi;
        g_WTlo[n * HH + k] = __float2bfloat16(x - __bfloat162float(hi));
    }
}

// ---------------------------------------------------------------------------
// Tensor-core output GEMM via mma.sync (sm_80 PTX; legal on sm_103 non-'a').
// C[8192, V] = S @ Wo.  Split bf16: D = Shi*Bhi + Shi*Blo + Slo*Bhi.
// Block 128m x 128n, 256 threads (8 warps, 2x4), warp tile 64m x 32n.
// 32 k-chunks of 32. smem tiles 128 x 32 bf16 at 80B row stride (bank-perfect
// for ldmatrix: 20r mod 32 tiles all banks).
#define RSB 80   // smem row stride bytes (40 bf16)

__global__ __launch_bounds__(256) void k_gemm_tc(float* __restrict__ C) {
    __shared__ __align__(16) char sm[4 * 128 * RSB];   // 40960 B
    const uint32_t sbase = smem_u32(sm);
    const uint32_t sAhi = sbase, sAlo = sbase + 10240;
    const uint32_t sBhi = sbase + 20480, sBlo = sbase + 30720;

    const int tid = threadIdx.x, lane = tid & 31, wid = tid >> 5;
    const int warp_m = wid >> 2, warp_n = wid & 3;   // 2 x 4
    const int mt = blockIdx.x * 128, nt = blockIdx.y * 128;

    float acc[4][4][4];
#pragma unroll
    for (int mi = 0; mi < 4; mi++)
#pragma unroll
        for (int ni = 0; ni < 4; ni++)
#pragma unroll
            for (int q = 0; q < 4; q++) acc[mi][ni][q] = 0.f;

    // ldmatrix lane addressing
    const int lm_mat = lane >> 3, lm_r = lane & 7;
    const int a_row_add = lm_r + ((lm_mat & 1) << 3);
    const int a_k_add   = (lm_mat >> 1) << 3;
    const int b_row_add = lm_r + ((lm_mat >> 1) << 3);
    const int b_k_add   = (lm_mat & 1) << 3;

    for (int ch = 0; ch < 32; ch++) {          // FIX: 32 chunks cover K=1024
        const int k0 = ch * 32;
        __syncthreads();
        // Stage 4 tiles of [128 x 32] bf16: 2048 uint4 total, 8 per thread.
#pragma unroll
        for (int j = 0; j < 8; j++) {
            int idx = tid + j * 256;           // 0..2047
            int tile = idx >> 9;               // 0..3
            int e = idx & 511;                 // uint4 within tile
            int r = e >> 2, q = e & 3;
            char* dst = sm + tile * 10240 + r * RSB + q * 16;
            const __nv_bfloat16* src;
            if (tile == 0)      src = &g_Shi[(mt + r) * HH + k0 + q * 8];
            else if (tile == 1) src = &g_Slo[(mt + r) * HH + k0 + q * 8];
            else if (tile == 2) src = &g_WThi[(nt + r) * HH + k0 + q * 8];
            else                src = &g_WTlo[(nt + r) * HH + k0 + q * 8];
            *(uint4*)dst = *(const uint4*)src;
        }
        __syncthreads();

#pragma unroll
        for (int kk = 0; kk < 32; kk += 16) {
            uint32_t ahi[4][4], alo[4][4], bhi[2][4], blo[2][4];
#pragma unroll
            for (int mi = 0; mi < 4; mi++) {
                int row = warp_m * 64 + mi * 16 + a_row_add;
                uint32_t off = (uint32_t)(row * RSB + (kk + a_k_add) * 2);
                ldsm_x4(ahi[mi], sAhi + off);
                ldsm_x4(alo[mi], sAlo + off);
            }
#pragma unroll
            for (int p = 0; p < 2; p++) {
                int row = warp_n * 32 + p * 16 + b_row_add;
                uint32_t off = (uint32_t)(row * RSB + (kk + b_k_add) * 2);
                ldsm_x4(bhi[p], sBhi + off);
                ldsm_x4(blo[p], sBlo + off);
            }
#pragma unroll
            for (int mi = 0; mi < 4; mi++)
#pragma unroll
                for (int ni = 0; ni < 4; ni++) {
                    const uint32_t* bh = &bhi[ni >> 1][(ni & 1) * 2];
                    const uint32_t* bl = &blo[ni >> 1][(ni & 1) * 2];
                    mma16816(acc[mi][ni], ahi[mi], bh);
                    mma16816(acc[mi][ni], ahi[mi], bl);
                    mma16816(acc[mi][ni], alo[mi], bh);
                }
        }
    }

    // Epilogue: c0:(g,2t) c1:(g,2t+1) c2:(g+8,2t) c3:(g+8,2t+1)
    const int g = lane >> 2, t2 = (lane & 3) * 2;
#pragma unroll
    for (int mi = 0; mi < 4; mi++) {
#pragma unroll
        for (int ni = 0; ni < 4; ni++) {
            int m0 = mt + warp_m * 64 + mi * 16 + g;
            int n0 = nt + warp_n * 32 + ni * 8 + t2;
            if (n0 < VV) {
                C[m0 * VV + n0] = acc[mi][ni][0];
                C[(m0 + 8) * VV + n0] = acc[mi][ni][2];
            }
            if (n0 + 1 < VV) {
                C[m0 * VV + n0 + 1] = acc[mi][ni][1];
                C[(m0 + 8) * VV + n0 + 1] = acc[mi][ni][3];
            }
        }
    }
}

// ---------------------------------------------------------------------------
__global__ void k_hfinal(float* __restrict__ out) {
    int i = blockIdx.x * blockDim.x + threadIdx.x;
    if (i < BB * HH) {
        int b = i / HH, k = i % HH;
        out[i] = g_h[k * BB + b];
    }
}

// ---------------------------------------------------------------------------
extern "C" void kernel_launch(void* const* d_in, const int* in_sizes, int n_in,
                              void* d_out, int out_size)
{
    const int*   items_raw = (const int*)d_in[0];
    const float* h0   = (const float*)d_in[1];
    const float* E_ru = (const float*)d_in[2];
    const float* W_ru = (const float*)d_in[3];
    const float* b_ru = (const float*)d_in[4];
    const float* E_c  = (const float*)d_in[5];
    const float* W_c  = (const float*)d_in[6];
    const float* b_c  = (const float*)d_in[7];
    const float* W_out = (const float*)d_in[8];

    float* out = (float*)d_out;
    float* logits = out + BB * HH;

    cudaFuncSetAttribute(k_rnn, cudaFuncAttributeMaxDynamicSharedMemorySize,
                         180224);

    k_init<<<(BB * HH + 255) / 256, 256>>>(h0);
    k_detect<<<(BB * TT / 2 + 255) / 256, 256>>>(items_raw);
    k_convert<<<(BB * TT + 255) / 256, 256>>>(items_raw);
    k_conv_w<<<(NPAD * HH + 255) / 256, 256>>>(W_out);

    k_rnn<<<NB, 512, 180224>>>(E_ru, b_ru, E_c, b_c, W_ru, W_c);

    k_conv_s<<<(BB * TT * HH + 255) / 256, 256>>>();

    dim3 ggrid((BB * TT) / 128, NPAD / 128);
    k_gemm_tc<<<ggrid, 256>>>(logits);

    k_hfinal<<<(BB * HH + 255) / 256, 256>>>(out);
}

// round 13
// speedup vs baseline: 2.0164x; 1.9595x over previous
#include <cuda_runtime.h>
#include <cuda_bf16.h>
#include <cstdint>

// CollaborativeRNN (GRU-like): B=32, T=256, H=1024, V=10001
// out = [h_final (B*H) | logits (B*T*V)]  (float32)

#define BB 32
#define TT 256
#define HH 1024
#define H2 2048
#define VV 10001
#define NB 128
#define NPAD 10112  // 79 * 128

typedef unsigned long long u64;

// State (row-major [b][k]) and scratch
__device__ float g_h[BB * HH];
__device__ float g_u[BB * HH];
__device__ __align__(16) __nv_bfloat16 g_hhi[BB * HH];
__device__ __align__(16) __nv_bfloat16 g_hlo[BB * HH];
__device__ __align__(16) __nv_bfloat16 g_rhhi[BB * HH];
__device__ __align__(16) __nv_bfloat16 g_rhlo[BB * HH];
__device__ int   g_items[BB * TT];
__device__ int   g_nzodd;
__device__ int   g_count;
__device__ volatile int g_gen;
__device__ __align__(16) __nv_bfloat16 g_Shi[BB * TT * HH];
__device__ __align__(16) __nv_bfloat16 g_Slo[BB * TT * HH];
__device__ __align__(16) __nv_bfloat16 g_WThi[NPAD * HH];   // W_out^T [n][k]
__device__ __align__(16) __nv_bfloat16 g_WTlo[NPAD * HH];

__device__ __forceinline__ uint32_t smem_u32(const void* p) {
    uint32_t a;
    asm("{ .reg .u64 t; cvta.to.shared.u64 t, %1; cvt.u32.u64 %0, t; }"
        : "=r"(a) : "l"(p));
    return a;
}
__device__ __forceinline__ void ldsm_x4(uint32_t* r, uint32_t addr) {
    asm volatile("ldmatrix.sync.aligned.m8n8.x4.shared.b16 {%0,%1,%2,%3}, [%4];"
                 : "=r"(r[0]), "=r"(r[1]), "=r"(r[2]), "=r"(r[3]) : "r"(addr));
}
__device__ __forceinline__ void ldsm_x2(uint32_t* r, uint32_t addr) {
    asm volatile("ldmatrix.sync.aligned.m8n8.x2.shared.b16 {%0,%1}, [%2];"
                 : "=r"(r[0]), "=r"(r[1]) : "r"(addr));
}
__device__ __forceinline__ void mma16816(float* c, const uint32_t* a,
                                         const uint32_t* b) {
    asm volatile(
        "mma.sync.aligned.m16n8k16.row.col.f32.bf16.bf16.f32 "
        "{%0,%1,%2,%3}, {%4,%5,%6,%7}, {%8,%9}, {%0,%1,%2,%3};"
        : "+f"(c[0]), "+f"(c[1]), "+f"(c[2]), "+f"(c[3])
        : "r"(a[0]), "r"(a[1]), "r"(a[2]), "r"(a[3]), "r"(b[0]), "r"(b[1]));
}
__device__ __forceinline__ void stg16(__nv_bfloat16* p, __nv_bfloat16 v) {
    unsigned short u = *(unsigned short*)&v;
    asm volatile("st.global.cg.u16 [%0], %1;" :: "l"(p), "h"(u));
}

// ---------------------------------------------------------------------------
__global__ void k_init(const float* __restrict__ h0) {
    int i = blockIdx.x * blockDim.x + threadIdx.x;
    if (i == 0) { g_nzodd = 0; g_count = 0; g_gen = 0; }
    if (i < BB * HH) {
        float x = h0[i];
        g_h[i] = x;
        __nv_bfloat16 hi = __float2bfloat16(x);
        g_hhi[i] = hi;
        g_hlo[i] = __float2bfloat16(x - __bfloat162float(hi));
    }
}
__global__ void k_detect(const int* __restrict__ w) {
    int i = blockIdx.x * blockDim.x + threadIdx.x;
    if (i < (BB * TT) / 2) {
        if (w[2 * i + 1] != 0) atomicOr(&g_nzodd, 1);
    }
}
__global__ void k_convert(const int* __restrict__ w) {
    int i = blockIdx.x * blockDim.x + threadIdx.x;
    if (i < BB * TT) g_items[i] = g_nzodd ? w[i] : w[2 * i];
}

// ---------------------------------------------------------------------------
__device__ __forceinline__ void gridbar() {
    __syncthreads();
    if (threadIdx.x == 0) {
        __threadfence();
        int gen = g_gen;
        if (atomicAdd(&g_count, 1) == NB - 1) {
            atomicExch(&g_count, 0);
            __threadfence();
            g_gen = gen + 1;
        } else {
            while (g_gen == gen) { __nanosleep(64); }
            __threadfence();
        }
    }
    __syncthreads();
}

// ---------------------------------------------------------------------------
// Tensor-core persistent recurrence. 128 blocks x 512 threads (16 warps).
// Block owns 16 cols of W_ru (blk*16..) and 8 cols of W_c (blk*8..), resident
// in smem as split-bf16 [n][k] rows (stride 1032 bf16 = 2064 B).
// h/rh staged per 256-k chunk as [32 m][k] (stride 264 bf16 = 528 B).
// K split across 16 warps (k-tile of 16 per chunk per warp); fp32 accum;
// smem tree reduction; split product: hi*Whi + hi*Wlo + lo*Whi.
#define RSW 1032   // W row stride (bf16 elements)
#define RSH 264    // h stage row stride (bf16 elements)
#define SM_WRUHI 0
#define SM_WRULO 33024
#define SM_WCHI  66048
#define SM_WCLO  82560
#define SM_HHI   99072
#define SM_HLO   115968
#define SM_RED   132864
#define SM_TOTAL 165632

__global__ __launch_bounds__(512) void k_rnn(
    const float* __restrict__ Eru, const float* __restrict__ bru,
    const float* __restrict__ Ec,  const float* __restrict__ bc,
    const float* __restrict__ Wru, const float* __restrict__ Wc)
{
    extern __shared__ char sm[];
    const uint32_t sb = smem_u32(sm);
    float* red = (float*)(sm + SM_RED);

    const int tid  = threadIdx.x;
    const int lane = tid & 31;
    const int wid  = tid >> 5;
    const int blk  = blockIdx.x;

    // One-time weight load + split conversion into smem
    for (int j = 0; j < 32; j++) {
        int i = tid + j * 512;               // 0..16383
        int n = i & 15, k = i >> 4;
        float x = Wru[k * H2 + blk * 16 + n];
        __nv_bfloat16 hi = __float2bfloat16(x);
        *(__nv_bfloat16*)(sm + SM_WRUHI + (n * RSW + k) * 2) = hi;
        *(__nv_bfloat16*)(sm + SM_WRULO + (n * RSW + k) * 2) =
            __float2bfloat16(x - __bfloat162float(hi));
    }
    for (int j = 0; j < 16; j++) {
        int i = tid + j * 512;               // 0..8191
        int n = i & 7, k = i >> 3;
        float x = Wc[k * HH + blk * 8 + n];
        __nv_bfloat16 hi = __float2bfloat16(x);
        *(__nv_bfloat16*)(sm + SM_WCHI + (n * RSW + k) * 2) = hi;
        *(__nv_bfloat16*)(sm + SM_WCLO + (n * RSW + k) * 2) =
            __float2bfloat16(x - __bfloat162float(hi));
    }

    // Output roles
    const int mA = tid >> 4, nA = tid & 15;       // phase A (512 outputs)
    const int colA = blk * 16 + nA;
    const float bAv = bru[colA];
    const int mB = tid >> 3, nB = tid & 7;        // phase B (256 outputs)
    const int colB = blk * 8 + nB;
    const float bBv = (tid < 256) ? bc[colB] : 0.f;

    // ldmatrix lane addressing (same mapping as validated GEMM)
    const int lm_mat = lane >> 3, lm_r = lane & 7;
    const int a_row_add = lm_r + ((lm_mat & 1) << 3);
    const int a_k_add   = (lm_mat >> 1) << 3;
    const int b_row_add = lm_r + ((lm_mat >> 1) << 3);
    const int b_k_add   = (lm_mat & 1) << 3;
    const int l16 = lane & 15;
    const int c_row = l16 & 7, c_k_add = (l16 >> 3) << 3;

    __syncthreads();

    for (int t = 0; t < TT; t++) {
        // ================= Phase A: ru gates =================
        float eA = Eru[g_items[mA * TT + t] * H2 + colA];
        float accA[2][2][4];
#pragma unroll
        for (int mi = 0; mi < 2; mi++)
#pragma unroll
            for (int ni = 0; ni < 2; ni++)
#pragma unroll
                for (int q = 0; q < 4; q++) accA[mi][ni][q] = 0.f;

#pragma unroll
        for (int c = 0; c < 4; c++) {
            __syncthreads();
#pragma unroll
            for (int j = 0; j < 2; j++) {
                int idx = tid + j * 512;     // 0..1023 uint4 units
                int mm = idx >> 5, q = idx & 31;
                *(uint4*)(sm + SM_HHI + mm * (RSH * 2) + q * 16) =
                    __ldcg((const uint4*)(g_hhi + mm * HH + c * 256 + q * 8));
                *(uint4*)(sm + SM_HLO + mm * (RSH * 2) + q * 16) =
                    __ldcg((const uint4*)(g_hlo + mm * HH + c * 256 + q * 8));
            }
            __syncthreads();
            const int kk = wid * 16;          // k within chunk
            const int kg = c * 256 + kk;      // global k (for W)
            uint32_t ahi[2][4], alo[2][4], bh[4], bl[4];
#pragma unroll
            for (int mi = 0; mi < 2; mi++) {
                uint32_t off = (uint32_t)((mi * 16 + a_row_add) * (RSH * 2) +
                                          (kk + a_k_add) * 2);
                ldsm_x4(ahi[mi], sb + SM_HHI + off);
                ldsm_x4(alo[mi], sb + SM_HLO + off);
            }
            {
                uint32_t off = (uint32_t)(b_row_add * (RSW * 2) +
                                          (kg + b_k_add) * 2);
                ldsm_x4(bh, sb + SM_WRUHI + off);
                ldsm_x4(bl, sb + SM_WRULO + off);
            }
#pragma unroll
            for (int mi = 0; mi < 2; mi++)
#pragma unroll
                for (int ni = 0; ni < 2; ni++) {
                    mma16816(accA[mi][ni], ahi[mi], &bh[ni * 2]);
                    mma16816(accA[mi][ni], ahi[mi], &bl[ni * 2]);
                    mma16816(accA[mi][ni], alo[mi], &bh[ni * 2]);
                }
        }
        __syncthreads();
#pragma unroll
        for (int mi = 0; mi < 2; mi++)
#pragma unroll
            for (int ni = 0; ni < 2; ni++)
                *(float4*)(red + (wid * 4 + mi * 2 + ni) * 128 + lane * 4) =
                    make_float4(accA[mi][ni][0], accA[mi][ni][1],
                                accA[mi][ni][2], accA[mi][ni][3]);
        __syncthreads();
        {
            int mi = mA >> 4, rm = mA & 15, ni = nA >> 3;
            int rl = ((rm & 7) << 2) | ((nA & 7) >> 1);
            int rg = ((rm >> 3) << 1) | (nA & 1);
            float s = eA + bAv;
            const float* rp = red + (mi * 2 + ni) * 128 + rl * 4 + rg;
#pragma unroll
            for (int w = 0; w < 16; w++) s += rp[w * 512];
            float p = 1.f / (1.f + __expf(-s));
            if (blk < 64) {              // r gate -> rh split bf16
                float h = __ldcg(&g_h[mA * HH + colA]);
                float rh = p * h;
                __nv_bfloat16 hi = __float2bfloat16(rh);
                stg16(&g_rhhi[mA * HH + colA], hi);
                stg16(&g_rhlo[mA * HH + colA],
                      __float2bfloat16(rh - __bfloat162float(hi)));
            } else {                     // u gate
                __stcg(&g_u[mA * HH + (colA - HH)], p);
            }
        }
        // Prefetch phase-B embedding (independent of barrier)
        float eB = 0.f;
        if (tid < 256) eB = Ec[g_items[mB * TT + t] * HH + colB];
        gridbar();

        // ================= Phase B: candidate + h update =================
        float accB[2][4];
#pragma unroll
        for (int mi = 0; mi < 2; mi++)
#pragma unroll
            for (int q = 0; q < 4; q++) accB[mi][q] = 0.f;

#pragma unroll
        for (int c = 0; c < 4; c++) {
            __syncthreads();
#pragma unroll
            for (int j = 0; j < 2; j++) {
                int idx = tid + j * 512;
                int mm = idx >> 5, q = idx & 31;
                *(uint4*)(sm + SM_HHI + mm * (RSH * 2) + q * 16) =
                    __ldcg((const uint4*)(g_rhhi + mm * HH + c * 256 + q * 8));
                *(uint4*)(sm + SM_HLO + mm * (RSH * 2) + q * 16) =
                    __ldcg((const uint4*)(g_rhlo + mm * HH + c * 256 + q * 8));
            }
            __syncthreads();
            const int kk = wid * 16;
            const int kg = c * 256 + kk;
            uint32_t ahi[2][4], alo[2][4], bh2[2], bl2[2];
#pragma unroll
            for (int mi = 0; mi < 2; mi++) {
                uint32_t off = (uint32_t)((mi * 16 + a_row_add) * (RSH * 2) +
                                          (kk + a_k_add) * 2);
                ldsm_x4(ahi[mi], sb + SM_HHI + off);
                ldsm_x4(alo[mi], sb + SM_HLO + off);
            }
            {
                uint32_t off = (uint32_t)(c_row * (RSW * 2) +
                                          (kg + c_k_add) * 2);
                ldsm_x2(bh2, sb + SM_WCHI + off);
                ldsm_x2(bl2, sb + SM_WCLO + off);
            }
#pragma unroll
            for (int mi = 0; mi < 2; mi++) {
                mma16816(accB[mi], ahi[mi], bh2);
                mma16816(accB[mi], ahi[mi], bl2);
                mma16816(accB[mi], alo[mi], bh2);
            }
        }
        __syncthreads();
#pragma unroll
        for (int mi = 0; mi < 2; mi++)
            *(float4*)(red + (wid * 2 + mi) * 128 + lane * 4) =
                make_float4(accB[mi][0], accB[mi][1], accB[mi][2], accB[mi][3]);
        __syncthreads();
        if (tid < 256) {
            int mi = mB >> 4, rm = mB & 15;
            int rl = ((rm & 7) << 2) | (nB >> 1);
            int rg = ((rm >> 3) << 1) | (nB & 1);
            float s = eB + bBv;
            const float* rp = red + mi * 128 + rl * 4 + rg;
#pragma unroll
            for (int w = 0; w < 16; w++) s += rp[w * 256];
            float cc = tanhf(s);
            float u = __ldcg(&g_u[mB * HH + colB]);
            float h = __ldcg(&g_h[mB * HH + colB]);
            float hn = u * h + (1.f - u) * cc;
            __stcg(&g_h[mB * HH + colB], hn);
            __nv_bfloat16 hi = __float2bfloat16(hn);
            __nv_bfloat16 lo = __float2bfloat16(hn - __bfloat162float(hi));
            stg16(&g_hhi[mB * HH + colB], hi);
            stg16(&g_hlo[mB * HH + colB], lo);
            stg16(&g_Shi[(mB * TT + t) * HH + colB], hi);
            stg16(&g_Slo[(mB * TT + t) * HH + colB], lo);
        }
        gridbar();
    }
}

// ---------------------------------------------------------------------------
__global__ void k_conv_w(const float* __restrict__ Wo) {
    int i = blockIdx.x * blockDim.x + threadIdx.x;
    if (i < NPAD * HH) {
        int n = i >> 10, k = i & 1023;
        float x = (n < VV) ? Wo[k * VV + n] : 0.0f;
        __nv_bfloat16 hi = __float2bfloat16(x);
        g_WThi[n * HH + k] = hi;
        g_WTlo[n * HH + k] = __float2bfloat16(x - __bfloat162float(hi));
    }
}

// ---------------------------------------------------------------------------
// Tensor-core output GEMM (validated R11). C[8192, V] = S @ Wo.
#define RSB 80   // smem row stride bytes (40 bf16)

__global__ __launch_bounds__(256) void k_gemm_tc(float* __restrict__ C) {
    __shared__ __align__(16) char smg[4 * 128 * RSB];   // 40960 B
    const uint32_t sbase = smem_u32(smg);
    const uint32_t sAhi = sbase, sAlo = sbase + 10240;
    const uint32_t sBhi = sbase + 20480, sBlo = sbase + 30720;

    const int tid = threadIdx.x, lane = tid & 31, wid = tid >> 5;
    const int warp_m = wid >> 2, warp_n = wid & 3;   // 2 x 4
    const int mt = blockIdx.x * 128, nt = blockIdx.y * 128;

    float acc[4][4][4];
#pragma unroll
    for (int mi = 0; mi < 4; mi++)
#pragma unroll
        for (int ni = 0; ni < 4; ni++)
#pragma unroll
            for (int q = 0; q < 4; q++) acc[mi][ni][q] = 0.f;

    const int lm_mat = lane >> 3, lm_r = lane & 7;
    const int a_row_add = lm_r + ((lm_mat & 1) << 3);
    const int a_k_add   = (lm_mat >> 1) << 3;
    const int b_row_add = lm_r + ((lm_mat >> 1) << 3);
    const int b_k_add   = (lm_mat & 1) << 3;

    for (int ch = 0; ch < 32; ch++) {
        const int k0 = ch * 32;
        __syncthreads();
#pragma unroll
        for (int j = 0; j < 8; j++) {
            int idx = tid + j * 256;
            int tile = idx >> 9;
            int e = idx & 511;
            int r = e >> 2, q = e & 3;
            char* dst = smg + tile * 10240 + r * RSB + q * 16;
            const __nv_bfloat16* src;
            if (tile == 0)      src = &g_Shi[(mt + r) * HH + k0 + q * 8];
            else if (tile == 1) src = &g_Slo[(mt + r) * HH + k0 + q * 8];
            else if (tile == 2) src = &g_WThi[(nt + r) * HH + k0 + q * 8];
            else                src = &g_WTlo[(nt + r) * HH + k0 + q * 8];
            *(uint4*)dst = *(const uint4*)src;
        }
        __syncthreads();

#pragma unroll
        for (int kk = 0; kk < 32; kk += 16) {
            uint32_t ahi[4][4], alo[4][4], bhi[2][4], blo[2][4];
#pragma unroll
            for (int mi = 0; mi < 4; mi++) {
                int row = warp_m * 64 + mi * 16 + a_row_add;
                uint32_t off = (uint32_t)(row * RSB + (kk + a_k_add) * 2);
                ldsm_x4(ahi[mi], sAhi + off);
                ldsm_x4(alo[mi], sAlo + off);
            }
#pragma unroll
            for (int p = 0; p < 2; p++) {
                int row = warp_n * 32 + p * 16 + b_row_add;
                uint32_t off = (uint32_t)(row * RSB + (kk + b_k_add) * 2);
                ldsm_x4(bhi[p], sBhi + off);
                ldsm_x4(blo[p], sBlo + off);
            }
#pragma unroll
            for (int mi = 0; mi < 4; mi++)
#pragma unroll
                for (int ni = 0; ni < 4; ni++) {
                    const uint32_t* bh = &bhi[ni >> 1][(ni & 1) * 2];
                    const uint32_t* bl = &blo[ni >> 1][(ni & 1) * 2];
                    mma16816(acc[mi][ni], ahi[mi], bh);
                    mma16816(acc[mi][ni], ahi[mi], bl);
                    mma16816(acc[mi][ni], alo[mi], bh);
                }
        }
    }

    const int g = lane >> 2, t2 = (lane & 3) * 2;
#pragma unroll
    for (int mi = 0; mi < 4; mi++) {
#pragma unroll
        for (int ni = 0; ni < 4; ni++) {
            int m0 = mt + warp_m * 64 + mi * 16 + g;
            int n0 = nt + warp_n * 32 + ni * 8 + t2;
            if (n0 < VV) {
                C[m0 * VV + n0] = acc[mi][ni][0];
                C[(m0 + 8) * VV + n0] = acc[mi][ni][2];
            }
            if (n0 + 1 < VV) {
                C[m0 * VV + n0 + 1] = acc[mi][ni][1];
                C[(m0 + 8) * VV + n0 + 1] = acc[mi][ni][3];
            }
        }
    }
}

// ---------------------------------------------------------------------------
__global__ void k_hfinal(float* __restrict__ out) {
    int i = blockIdx.x * blockDim.x + threadIdx.x;
    if (i < BB * HH) out[i] = g_h[i];
}

// ---------------------------------------------------------------------------
extern "C" void kernel_launch(void* const* d_in, const int* in_sizes, int n_in,
                              void* d_out, int out_size)
{
    const int*   items_raw = (const int*)d_in[0];
    const float* h0   = (const float*)d_in[1];
    const float* E_ru = (const float*)d_in[2];
    const float* W_ru = (const float*)d_in[3];
    const float* b_ru = (const float*)d_in[4];
    const float* E_c  = (const float*)d_in[5];
    const float* W_c  = (const float*)d_in[6];
    const float* b_c  = (const float*)d_in[7];
    const float* W_out = (const float*)d_in[8];

    float* out = (float*)d_out;
    float* logits = out + BB * HH;

    cudaFuncSetAttribute(k_rnn, cudaFuncAttributeMaxDynamicSharedMemorySize,
                         SM_TOTAL);

    k_init<<<(BB * HH + 255) / 256, 256>>>(h0);
    k_detect<<<(BB * TT / 2 + 255) / 256, 256>>>(items_raw);
    k_convert<<<(BB * TT + 255) / 256, 256>>>(items_raw);
    k_conv_w<<<(NPAD * HH + 255) / 256, 256>>>(W_out);

    k_rnn<<<NB, 512, SM_TOTAL>>>(E_ru, b_ru, E_c, b_c, W_ru, W_c);

    dim3 ggrid((BB * TT) / 128, NPAD / 128);
    k_gemm_tc<<<ggrid, 256>>>(logits);

    k_hfinal<<<(BB * HH + 255) / 256, 256>>>(out);
}